// round 14
// baseline (speedup 1.0000x reference)
#include <cuda_runtime.h>
#include <cuda_bf16.h>
#include <cstdint>

// ============================================================================
// CAM via Gram restructuring, mma.sync bf16 hi/lo.
// R14: LDS.128 slot layout (conflict-free, S ≡ 16 mod 32) for A/B fragments.
// Slot fm of a (row, kgroup) holds [hi_fm, lo_fm, hi_{fm+4}, lo_{fm+4}].
// ============================================================================

#define NPIX   65536
#define JT     208
#define SPLITS 37
#define GCH    64     // gram pixels per chunk
#define SQW    80     // gram smem row stride in words (80 mod 32 == 16)
#define ASW    208    // out A smem row stride in words (208 mod 32 == 16)
#define OXS    136    // out X smem stride (bf16)
#define OTN    128    // out pixels per CTA

__device__ unsigned short g_Xhi[4 * 192 * NPIX];
__device__ unsigned short g_Xlo[4 * 192 * NPIX];
__device__ float g_Gp[4 * SPLITS * JT * JT];
__device__ float g_G[4 * JT * JT];
__device__ float g_T2[4 * 193 * 64];
__device__ unsigned short g_Mhi[4 * 64 * JT];
__device__ unsigned short g_Mlo[4 * 64 * JT];

// ---------------------------------------------------------------------------
static __device__ __forceinline__ uint32_t smem_u32(const void* p) {
    uint32_t a;
    asm("{ .reg .u64 t; cvta.to.shared.u64 t, %1; cvt.u32.u64 %0, t; }"
        : "=r"(a) : "l"(p));
    return a;
}

#define MMA16816(d, a0, a1, a2, a3, b0, b1) \
    asm volatile("mma.sync.aligned.m16n8k16.row.col.f32.bf16.bf16.f32 " \
        "{%0,%1,%2,%3}, {%4,%5,%6,%7}, {%8,%9}, {%0,%1,%2,%3};" \
        : "+f"((d)[0]), "+f"((d)[1]), "+f"((d)[2]), "+f"((d)[3]) \
        : "r"(a0), "r"(a1), "r"(a2), "r"(a3), "r"(b0), "r"(b1))

#define LDSM_X2_T(r0, r1, addr) \
    asm volatile("ldmatrix.sync.aligned.m8n8.x2.trans.shared.b16 {%0,%1}, [%2];" \
        : "=r"(r0), "=r"(r1) : "r"(addr))

static __device__ __forceinline__ void split_bf16(float x, unsigned short& h,
                                                  unsigned short& lo) {
    __nv_bfloat16 hb = __float2bfloat16(x);
    __nv_bfloat16 lb = __float2bfloat16(x - __bfloat162float(hb));
    h = __bfloat16_as_ushort(hb);
    lo = __bfloat16_as_ushort(lb);
}

__global__ void cam_nop() {}

// ---------------------------------------------------------------------------
// kernel 0: pre-split X -> global bf16 hi/lo planes (DRAM-bound)
// ---------------------------------------------------------------------------
__global__ __launch_bounds__(256)
void cam_presplit(const float* __restrict__ rgb,
                  const float* __restrict__ hsv,
                  const float* __restrict__ lab) {
    const int b = blockIdx.y;
    const int u = blockIdx.x * 256 + threadIdx.x;
    const int px8 = u * 8;
    const int ch = px8 >> 16;
    const int px = px8 & 65535;

    const float* bases[3] = {
        rgb + (size_t)b * 64 * NPIX,
        hsv + (size_t)b * 64 * NPIX,
        lab + (size_t)b * 64 * NPIX
    };
    const float* src = bases[ch >> 6] + (size_t)(ch & 63) * NPIX + px;

    const float4 v0 = *(const float4*)src;
    const float4 v1 = *(const float4*)(src + 4);

    unsigned short h[8], l[8];
    split_bf16(v0.x, h[0], l[0]); split_bf16(v0.y, h[1], l[1]);
    split_bf16(v0.z, h[2], l[2]); split_bf16(v0.w, h[3], l[3]);
    split_bf16(v1.x, h[4], l[4]); split_bf16(v1.y, h[5], l[5]);
    split_bf16(v1.z, h[6], l[6]); split_bf16(v1.w, h[7], l[7]);

    uint4 hv, lv;
    hv.x = (uint32_t)h[0] | ((uint32_t)h[1] << 16);
    hv.y = (uint32_t)h[2] | ((uint32_t)h[3] << 16);
    hv.z = (uint32_t)h[4] | ((uint32_t)h[5] << 16);
    hv.w = (uint32_t)h[6] | ((uint32_t)h[7] << 16);
    lv.x = (uint32_t)l[0] | ((uint32_t)l[1] << 16);
    lv.y = (uint32_t)l[2] | ((uint32_t)l[3] << 16);
    lv.z = (uint32_t)l[4] | ((uint32_t)l[5] << 16);
    lv.w = (uint32_t)l[6] | ((uint32_t)l[7] << 16);

    const size_t off = ((size_t)(b * 192 + ch) << 16) + px;
    *(uint4*)(g_Xhi + off) = hv;
    *(uint4*)(g_Xlo + off) = lv;
}

// ---------------------------------------------------------------------------
// kernel 1: split-K Gram.  Slot layout: word(row j, group g, slot fm, q) =
// j*SQW + g*16 + fm*4 + q, q in {0:hi_fm, 1:lo_fm, 2:hi_{fm+4}, 3:lo_{fm+4}}
// ---------------------------------------------------------------------------
#define GRAM_SMEM (JT * SQW * 4)

__global__ __launch_bounds__(512, 2)
void cam_gram_mma() {
    extern __shared__ __align__(16) uint32_t gsm[];

    const int tid = threadIdx.x;
    const int l = tid & 31;
    const int w = tid >> 5;       // 0..15
    const int split = blockIdx.x;
    const int b = blockIdx.y;
    const int z = blockIdx.z;     // tile half
    const int fr = l >> 2;
    const int fm = l & 3;

    // static rows 192..207: row 192 hi slots (word%4 in {0,2}) = 1.0, else 0
    for (int idx = tid; idx < 16 * SQW; idx += 512) {
        const int r = idx / SQW;
        const int q = idx % SQW;
        gsm[(192 + r) * SQW + q] =
            (r == 0 && ((q & 3) == 0 || (q & 3) == 2)) ? 0x3F803F80u : 0u;
    }

    // tiles [z*91, z*91+91): per warp 6 (w<11) or 5 (w>=11)
    const int startL = (w < 11) ? 6 * w : 66 + 5 * (w - 11);
    const int cnt = (w < 11) ? 6 : 5;
    const int start = z * 91 + startL;
    int mtA[6], ntA[6];
    {
        int rem = start, mt = 0;
        while (mt < 13 && rem >= 26 - 2 * mt) { rem -= 26 - 2 * mt; mt++; }
        int nt = 2 * mt + rem;
#pragma unroll
        for (int t = 0; t < 6; t++) {
            if (mt >= 13) { mt = 12; nt = 25; }
            mtA[t] = mt; ntA[t] = nt;
            nt++;
            if (nt >= 26) { mt++; nt = 2 * mt; }
        }
    }

    // precomputed row offsets (words)
    int aOff[6], bOff[6];
#pragma unroll
    for (int t = 0; t < 6; t++) {
        aOff[t] = (mtA[t] * 16 + fr) * SQW;
        bOff[t] = (ntA[t] * 8 + fr) * SQW;
    }

    float acc[6][4];
#pragma unroll
    for (int t = 0; t < 6; t++)
#pragma unroll
        for (int q = 0; q < 4; q++) acc[t][q] = 0.0f;

    for (int chunk = split; chunk < NPIX / GCH; chunk += SPLITS) {
        const int n0 = chunk * GCH;
        __syncthreads();
        // stage rows 0..191: units = (row, group); 768 units
        for (int u = tid; u < 192 * 4; u += 512) {
            const int j = u >> 2;
            const int g = u & 3;
            const size_t goff = ((size_t)(b * 192 + j) << 16) + n0 + g * 16;
            const uint4 ha = *(const uint4*)(g_Xhi + goff);      // pairs 0-3
            const uint4 hb = *(const uint4*)(g_Xhi + goff + 8);  // pairs 4-7
            const uint4 la = *(const uint4*)(g_Xlo + goff);
            const uint4 lb = *(const uint4*)(g_Xlo + goff + 8);
            uint32_t* dst = gsm + j * SQW + g * 16;
            *(uint4*)(dst + 0)  = make_uint4(ha.x, la.x, hb.x, lb.x);
            *(uint4*)(dst + 4)  = make_uint4(ha.y, la.y, hb.y, lb.y);
            *(uint4*)(dst + 8)  = make_uint4(ha.z, la.z, hb.z, lb.z);
            *(uint4*)(dst + 12) = make_uint4(ha.w, la.w, hb.w, lb.w);
        }
        __syncthreads();

#pragma unroll 1
        for (int g = 0; g < GCH / 16; g++) {
            const int kW = g * 16 + 4 * fm;
            int prev = -1;
            uint4 A0 = make_uint4(0, 0, 0, 0);
            uint4 A1 = make_uint4(0, 0, 0, 0);
#pragma unroll
            for (int t = 0; t < 6; t++) {
                if (t < cnt) {
                    if (mtA[t] != prev) {
                        prev = mtA[t];
                        A0 = *(const uint4*)(gsm + aOff[t] + kW);            // (ah0,al0,ah2,al2)
                        A1 = *(const uint4*)(gsm + aOff[t] + 8 * SQW + kW);  // (ah1,al1,ah3,al3)
                    }
                    const uint4 B0 = *(const uint4*)(gsm + bOff[t] + kW);    // (bh0,bl0,bh1,bl1)
                    MMA16816(acc[t], A0.x, A1.x, A0.z, A1.z, B0.x, B0.z);    // hi*hi
                    MMA16816(acc[t], A0.x, A1.x, A0.z, A1.z, B0.y, B0.w);    // hi*lo
                    MMA16816(acc[t], A0.y, A1.y, A0.w, A1.w, B0.x, B0.z);    // lo*hi
                }
            }
        }
    }

    float* gp = g_Gp + (size_t)(b * SPLITS + split) * JT * JT;
#pragma unroll
    for (int t = 0; t < 6; t++) {
        if (t < cnt) {
            const int i0 = mtA[t] * 16 + fr;
            const int j0 = ntA[t] * 8 + 2 * fm;
            *(float2*)&gp[(size_t)i0 * JT + j0] = make_float2(acc[t][0], acc[t][1]);
            *(float2*)&gp[(size_t)(i0 + 8) * JT + j0] = make_float2(acc[t][2], acc[t][3]);
        }
    }
}

// ---------------------------------------------------------------------------
// kernel 2: reduce split-K + mirror
// ---------------------------------------------------------------------------
__global__ void cam_reduceG() {
    const int idx = blockIdx.x * 256 + threadIdx.x;
    const int b = idx / (JT * JT);
    const int rc = idx % (JT * JT);
    const int i = rc / JT, j = rc % JT;
    if (i > j) return;
    const float* gp = g_Gp + (size_t)b * SPLITS * JT * JT + rc;
    float acc = 0.0f;
#pragma unroll 4
    for (int s = 0; s < SPLITS; s++) acc += gp[(size_t)s * JT * JT];
    float* G = g_G + (size_t)b * JT * JT;
    G[i * JT + j] = acc;
    G[j * JT + i] = acc;
}

// ---------------------------------------------------------------------------
// kernel 3: T2[b][i][d] = sum_j G[b][i][j] Wk_aug[d][j]
// ---------------------------------------------------------------------------
__global__ void cam_projT2(const float* __restrict__ Wk,
                           const float* __restrict__ bk) {
    __shared__ float Gs[4][200];
    const int b = blockIdx.y;
    const int i0 = blockIdx.x * 4;
    const int tid = threadIdx.x;

    for (int idx = tid; idx < 4 * 193; idx += 256) {
        const int ii = idx / 193, j = idx % 193;
        if (i0 + ii < 193)
            Gs[ii][j] = g_G[(size_t)b * JT * JT + (size_t)(i0 + ii) * JT + j];
    }
    __syncthreads();

    const int d = tid & 63;
    const int ii = tid >> 6;
    const int i = i0 + ii;
    if (i < 193) {
        float acc = 0.0f;
#pragma unroll 4
        for (int j = 0; j < 192; j++) acc += Wk[d * 192 + j] * Gs[ii][j];
        acc += bk[d] * Gs[ii][192];
        g_T2[(size_t)b * 193 * 64 + i * 64 + d] = acc;
    }
}

// ---------------------------------------------------------------------------
// kernel 4: energy + softmax + M row, fused  (grid (64,4), 256 threads)
// ---------------------------------------------------------------------------
__global__ void cam_energyM(const float* __restrict__ Wq,
                            const float* __restrict__ bq,
                            const float* __restrict__ Wv,
                            const float* __restrict__ bv) {
    __shared__ float part[4][64];
    __shared__ float se[64];
    __shared__ float As[64];
    const int c = blockIdx.x;
    const int b = blockIdx.y;
    const int d = threadIdx.x & 63;
    const int ic = threadIdx.x >> 6;

    const float* T2b = g_T2 + (size_t)b * 193 * 64;
    const int ibeg = ic * 48;
    float e = 0.0f;
#pragma unroll 4
    for (int k = 0; k < 48; k++)
        e += Wq[c * 192 + ibeg + k] * T2b[(ibeg + k) * 64 + d];
    if (ic == 3) e += bq[c] * T2b[192 * 64 + d];
    part[ic][d] = e;
    __syncthreads();

    if (threadIdx.x < 64)
        se[d] = (part[0][d] + part[1][d] + part[2][d] + part[3][d]) * 0.125f;
    __syncthreads();

    if (threadIdx.x < 64) {
        const float e0 = se[d];
        float mx = -1e30f;
#pragma unroll 4
        for (int k = 0; k < 64; k++) mx = fmaxf(mx, se[k]);
        float s = 0.0f;
#pragma unroll 4
        for (int k = 0; k < 64; k++) s += expf(se[k] - mx);
        As[d] = expf(e0 - mx) / s;
    }
    __syncthreads();

    const int j = threadIdx.x;
    if (j < JT) {
        float m = 0.0f;
        if (j < 192) {
#pragma unroll 4
            for (int dd = 0; dd < 64; dd++) m += As[dd] * Wv[dd * 192 + j];
        } else if (j == 192) {
#pragma unroll 4
            for (int dd = 0; dd < 64; dd++) m += As[dd] * bv[dd];
        }
        unsigned short h, lo;
        split_bf16(m, h, lo);
        g_Mhi[(size_t)(b * 64 + c) * JT + j] = h;
        g_Mlo[(size_t)(b * 64 + c) * JT + j] = lo;
    }
}

// ---------------------------------------------------------------------------
// kernel 5: out[b] = M X_aug.  A in slot layout (LDS.128), X via ldmatrix.
// ---------------------------------------------------------------------------
#define OUT_SMEM (64 * ASW * 4 + 2 * 64 * OXS * 2)

__global__ __launch_bounds__(256, 2)
void cam_out_mma(float* __restrict__ out) {
    extern __shared__ __align__(16) char osm[];
    uint32_t* Aint = (uint32_t*)osm;                            // [64][208] words
    __nv_bfloat16* Xhi = (__nv_bfloat16*)(osm + 64 * ASW * 4);  // [64][136]
    __nv_bfloat16* Xlo = Xhi + 64 * OXS;

    const int tid = threadIdx.x;
    const int l = tid & 31;
    const int w = tid >> 5;
    const int wm = w >> 2;
    const int wn = w & 3;
    const int b = blockIdx.y;
    const int px0 = blockIdx.x * OTN;
    const int fr = l >> 2;
    const int fm = l & 3;

    // stage A in slot layout: units = (c, g), g in 0..12
    const uint32_t* mhi = (const uint32_t*)(g_Mhi + (size_t)b * 64 * JT);
    const uint32_t* mlo = (const uint32_t*)(g_Mlo + (size_t)b * 64 * JT);
    for (int u = tid; u < 64 * 13; u += 256) {
        const int c = u / 13;
        const int g = u % 13;
        const uint4 ha = *(const uint4*)(mhi + c * 104 + 8 * g);
        const uint4 hb = *(const uint4*)(mhi + c * 104 + 8 * g + 4);
        const uint4 la = *(const uint4*)(mlo + c * 104 + 8 * g);
        const uint4 lb = *(const uint4*)(mlo + c * 104 + 8 * g + 4);
        uint32_t* dst = Aint + c * ASW + g * 16;
        *(uint4*)(dst + 0)  = make_uint4(ha.x, la.x, hb.x, lb.x);
        *(uint4*)(dst + 4)  = make_uint4(ha.y, la.y, hb.y, lb.y);
        *(uint4*)(dst + 8)  = make_uint4(ha.z, la.z, hb.z, lb.z);
        *(uint4*)(dst + 12) = make_uint4(ha.w, la.w, hb.w, lb.w);
    }

    float acc[2][4][4];
#pragma unroll
    for (int mi = 0; mi < 2; mi++)
#pragma unroll
        for (int nt = 0; nt < 4; nt++)
#pragma unroll
            for (int q = 0; q < 4; q++) acc[mi][nt][q] = 0.0f;

    const uint32_t xhiB = smem_u32(Xhi);
    const uint32_t xloB = smem_u32(Xlo);

    for (int kc = 0; kc < JT; kc += 64) {
        const int klen = (kc + 64 <= JT) ? 64 : (JT - kc);
        __syncthreads();
        if (kc < 192) {
            for (int u2 = tid; u2 < klen * 16 * 2; u2 += 256) {
                const int plane = (u2 >= klen * 16) ? 1 : 0;
                const int uu = plane ? (u2 - klen * 16) : u2;
                const int kr = uu >> 4;
                const int q = uu & 15;
                const unsigned short* srcp = (plane ? g_Xlo : g_Xhi) +
                    (((size_t)(b * 192 + kc + kr)) << 16) + px0 + q * 8;
                *((uint4*)((plane ? Xlo : Xhi) + kr * OXS) + q) = *(const uint4*)srcp;
            }
        } else {
            for (int u2 = tid; u2 < 16 * 16 * 2; u2 += 256) {
                const int plane = (u2 >= 256) ? 1 : 0;
                const int uu = plane ? (u2 - 256) : u2;
                const int kr = uu >> 4;
                const int q = uu & 15;
                const uint4 val = (plane == 0 && kr == 0)
                    ? make_uint4(0x3F803F80u, 0x3F803F80u, 0x3F803F80u, 0x3F803F80u)
                    : make_uint4(0u, 0u, 0u, 0u);
                *((uint4*)((plane ? Xlo : Xhi) + kr * OXS) + q) = val;
            }
        }
        __syncthreads();

        const int nks = klen / 16;
#pragma unroll 1
        for (int ks = 0; ks < nks; ks++) {
            const int gg = (kc >> 4) + ks;
            uint32_t AH[2][4], AL[2][4];
#pragma unroll
            for (int mi = 0; mi < 2; mi++) {
                const int arow = (wm * 2 + mi) * 16 + fr;
                const uint32_t* ap = Aint + arow * ASW + gg * 16 + 4 * fm;
                const uint4 A0 = *(const uint4*)ap;              // (ah0,al0,ah2,al2)
                const uint4 A1 = *(const uint4*)(ap + 8 * ASW);  // (ah1,al1,ah3,al3)
                AH[mi][0] = A0.x; AL[mi][0] = A0.y;
                AH[mi][2] = A0.z; AL[mi][2] = A0.w;
                AH[mi][1] = A1.x; AL[mi][1] = A1.y;
                AH[mi][3] = A1.z; AL[mi][3] = A1.w;
            }
            const uint32_t rowoff = (uint32_t)(ks * 16 + (l & 15)) * (OXS * 2);
#pragma unroll
            for (int nt = 0; nt < 4; nt++) {
                const uint32_t coloff = (uint32_t)(wn * 32 + nt * 8) * 2;
                uint32_t bh0, bh1, bl0, bl1;
                LDSM_X2_T(bh0, bh1, xhiB + rowoff + coloff);
                LDSM_X2_T(bl0, bl1, xloB + rowoff + coloff);
#pragma unroll
                for (int mi = 0; mi < 2; mi++) {
                    MMA16816(acc[mi][nt], AH[mi][0], AH[mi][1], AH[mi][2], AH[mi][3], bh0, bh1);
                    MMA16816(acc[mi][nt], AH[mi][0], AH[mi][1], AH[mi][2], AH[mi][3], bl0, bl1);
                    MMA16816(acc[mi][nt], AL[mi][0], AL[mi][1], AL[mi][2], AL[mi][3], bh0, bh1);
                }
            }
        }
    }

#pragma unroll
    for (int mi = 0; mi < 2; mi++) {
        const int c0 = (wm * 2 + mi) * 16 + fr;
#pragma unroll
        for (int nt = 0; nt < 4; nt++) {
            const int px = px0 + wn * 32 + nt * 8 + 2 * fm;
            float* op = out + (size_t)(b * 64 + c0) * NPIX + px;
            *(float2*)op = make_float2(acc[mi][nt][0], acc[mi][nt][1]);
            *(float2*)(op + 8 * NPIX) = make_float2(acc[mi][nt][2], acc[mi][nt][3]);
        }
    }
}

// ---------------------------------------------------------------------------
// launch — presplit + 2 nops keep cam_gram_mma in profiled slot #4
// ---------------------------------------------------------------------------
extern "C" void kernel_launch(void* const* d_in, const int* in_sizes, int n_in,
                              void* d_out, int out_size) {
    const float* rgb = (const float*)d_in[0];
    const float* hsv = (const float*)d_in[1];
    const float* lab = (const float*)d_in[2];
    const float* Wq  = (const float*)d_in[3];
    const float* bq  = (const float*)d_in[4];
    const float* Wk  = (const float*)d_in[5];
    const float* bk  = (const float*)d_in[6];
    const float* Wv  = (const float*)d_in[7];
    const float* bv  = (const float*)d_in[8];
    float* out = (float*)d_out;

    cudaFuncSetAttribute(cam_gram_mma, cudaFuncAttributeMaxDynamicSharedMemorySize, GRAM_SMEM);
    cudaFuncSetAttribute(cam_out_mma, cudaFuncAttributeMaxDynamicSharedMemorySize, OUT_SMEM);

    cam_presplit<<<dim3(6144, 4), 256>>>(rgb, hsv, lab);
    cam_nop<<<1, 32>>>();
    cam_nop<<<1, 32>>>();
    cam_gram_mma<<<dim3(SPLITS, 4, 2), 512, GRAM_SMEM>>>();
    cam_reduceG<<<(4 * JT * JT) / 256, 256>>>();
    cam_projT2<<<dim3(49, 4), 256>>>(Wk, bk);
    cam_energyM<<<dim3(64, 4), 256>>>(Wq, bq, Wv, bv);
    cam_out_mma<<<dim3(NPIX / OTN, 4), 256, OUT_SMEM>>>(out);
}

// round 15
// speedup vs baseline: 1.2205x; 1.2205x over previous
#include <cuda_runtime.h>
#include <cuda_bf16.h>
#include <cstdint>

// ============================================================================
// CAM via Gram restructuring, mma.sync bf16 hi/lo (R12 fragment paths).
// R15: cp.async staging — double-buffered in gram, register-free in out.
// ============================================================================

#define NPIX   65536
#define JT     208
#define SPLITS 37
#define GCH    128    // gram pixels per chunk
#define GW     68     // gram smem words per row (64 data + 4 pad)
#define GPLANE (JT * GW)        // words per plane
#define GBUF   (2 * GPLANE)     // words per buffer (hi+lo)
#define ASTR   216    // out A smem stride (bf16)
#define OXS    136    // out X smem stride (bf16)
#define OTN    128    // out pixels per CTA

__device__ unsigned short g_Xhi[4 * 192 * NPIX];
__device__ unsigned short g_Xlo[4 * 192 * NPIX];
__device__ float g_Gp[4 * SPLITS * JT * JT];
__device__ float g_G[4 * JT * JT];
__device__ float g_T2[4 * 193 * 64];
__device__ unsigned short g_Mhi[4 * 64 * JT];
__device__ unsigned short g_Mlo[4 * 64 * JT];

// ---------------------------------------------------------------------------
static __device__ __forceinline__ uint32_t smem_u32(const void* p) {
    uint32_t a;
    asm("{ .reg .u64 t; cvta.to.shared.u64 t, %1; cvt.u32.u64 %0, t; }"
        : "=r"(a) : "l"(p));
    return a;
}

#define MMA16816(d, a0, a1, a2, a3, b0, b1) \
    asm volatile("mma.sync.aligned.m16n8k16.row.col.f32.bf16.bf16.f32 " \
        "{%0,%1,%2,%3}, {%4,%5,%6,%7}, {%8,%9}, {%0,%1,%2,%3};" \
        : "+f"((d)[0]), "+f"((d)[1]), "+f"((d)[2]), "+f"((d)[3]) \
        : "r"(a0), "r"(a1), "r"(a2), "r"(a3), "r"(b0), "r"(b1))

#define LDSM_X2_T(r0, r1, addr) \
    asm volatile("ldmatrix.sync.aligned.m8n8.x2.trans.shared.b16 {%0,%1}, [%2];" \
        : "=r"(r0), "=r"(r1) : "r"(addr))

#define CP_ASYNC16(dst, src) \
    asm volatile("cp.async.cg.shared.global [%0], [%1], 16;" \
        :: "r"(dst), "l"(src))
#define CP_COMMIT() asm volatile("cp.async.commit_group;" ::: "memory")
#define CP_WAIT(n)  asm volatile("cp.async.wait_group %0;" :: "n"(n) : "memory")

static __device__ __forceinline__ void split_bf16(float x, unsigned short& h,
                                                  unsigned short& lo) {
    __nv_bfloat16 hb = __float2bfloat16(x);
    __nv_bfloat16 lb = __float2bfloat16(x - __bfloat162float(hb));
    h = __bfloat16_as_ushort(hb);
    lo = __bfloat16_as_ushort(lb);
}

__global__ void cam_nop() {}

// ---------------------------------------------------------------------------
// kernel 0: pre-split X -> global bf16 hi/lo planes (DRAM-bound)
// ---------------------------------------------------------------------------
__global__ __launch_bounds__(256)
void cam_presplit(const float* __restrict__ rgb,
                  const float* __restrict__ hsv,
                  const float* __restrict__ lab) {
    const int b = blockIdx.y;
    const int u = blockIdx.x * 256 + threadIdx.x;
    const int px8 = u * 8;
    const int ch = px8 >> 16;
    const int px = px8 & 65535;

    const float* bases[3] = {
        rgb + (size_t)b * 64 * NPIX,
        hsv + (size_t)b * 64 * NPIX,
        lab + (size_t)b * 64 * NPIX
    };
    const float* src = bases[ch >> 6] + (size_t)(ch & 63) * NPIX + px;

    const float4 v0 = *(const float4*)src;
    const float4 v1 = *(const float4*)(src + 4);

    unsigned short h[8], l[8];
    split_bf16(v0.x, h[0], l[0]); split_bf16(v0.y, h[1], l[1]);
    split_bf16(v0.z, h[2], l[2]); split_bf16(v0.w, h[3], l[3]);
    split_bf16(v1.x, h[4], l[4]); split_bf16(v1.y, h[5], l[5]);
    split_bf16(v1.z, h[6], l[6]); split_bf16(v1.w, h[7], l[7]);

    uint4 hv, lv;
    hv.x = (uint32_t)h[0] | ((uint32_t)h[1] << 16);
    hv.y = (uint32_t)h[2] | ((uint32_t)h[3] << 16);
    hv.z = (uint32_t)h[4] | ((uint32_t)h[5] << 16);
    hv.w = (uint32_t)h[6] | ((uint32_t)h[7] << 16);
    lv.x = (uint32_t)l[0] | ((uint32_t)l[1] << 16);
    lv.y = (uint32_t)l[2] | ((uint32_t)l[3] << 16);
    lv.z = (uint32_t)l[4] | ((uint32_t)l[5] << 16);
    lv.w = (uint32_t)l[6] | ((uint32_t)l[7] << 16);

    const size_t off = ((size_t)(b * 192 + ch) << 16) + px;
    *(uint4*)(g_Xhi + off) = hv;
    *(uint4*)(g_Xlo + off) = lv;
}

// ---------------------------------------------------------------------------
// kernel 1: split-K Gram — R12 fragment path + cp.async double buffering.
// smem: 2 buffers x (hi plane [208][68]w + lo plane [208][68]w)
// ---------------------------------------------------------------------------
#define GRAM_SMEM (2 * GBUF * 4)

__global__ __launch_bounds__(512, 1)
void cam_gram_mma() {
    extern __shared__ __align__(16) uint32_t gsm[];

    const int tid = threadIdx.x;
    const int l = tid & 31;
    const int w = tid >> 5;       // 0..15
    const int split = blockIdx.x;
    const int b = blockIdx.y;
    const int z = blockIdx.z;     // tile half

    // static rows 192..207 in BOTH buffers (row 192 hi data words = 1.0)
    for (int idx = tid; idx < 2 * 2 * 16 * GW; idx += 512) {
        const int buf = idx / (2 * 16 * GW);
        const int rem = idx % (2 * 16 * GW);
        const int pl = rem / (16 * GW);
        const int r = (rem / GW) % 16;
        const int q = rem % GW;
        gsm[buf * GBUF + pl * GPLANE + (192 + r) * GW + q] =
            (pl == 0 && r == 0 && q < 64) ? 0x3F803F80u : 0u;
    }

    // tiles [z*91, z*91+91): per warp 6 (w<11) or 5 (w>=11)
    const int startL = (w < 11) ? 6 * w : 66 + 5 * (w - 11);
    const int cnt = (w < 11) ? 6 : 5;
    const int start = z * 91 + startL;
    int mtA[6], ntA[6];
    {
        int rem = start, mt = 0;
        while (mt < 13 && rem >= 26 - 2 * mt) { rem -= 26 - 2 * mt; mt++; }
        int nt = 2 * mt + rem;
#pragma unroll
        for (int t = 0; t < 6; t++) {
            if (mt >= 13) { mt = 12; nt = 25; }
            mtA[t] = mt; ntA[t] = nt;
            nt++;
            if (nt >= 26) { mt++; nt = 2 * mt; }
        }
    }

    float acc[6][4];
#pragma unroll
    for (int t = 0; t < 6; t++)
#pragma unroll
        for (int q = 0; q < 4; q++) acc[t][q] = 0.0f;

    const uint32_t smBase = smem_u32(gsm);
    const int nChunks = (NPIX / GCH - split + SPLITS - 1) / SPLITS;

    // stage chunk (ci-th local chunk) into buffer bi via cp.async (no commit)
    auto stage = [&](int ci, int bi) {
        const int n0 = (split + ci * SPLITS) * GCH;
        // units: (plane, row j, 16B group q of 4) -> 192*16 per plane
        for (int u2 = tid; u2 < 192 * 16 * 2; u2 += 512) {
            const int plane = (u2 >= 3072) ? 1 : 0;
            const int uu = plane ? (u2 - 3072) : u2;
            const int j = uu >> 4;
            const int q = uu & 15;
            const unsigned short* srcp = (plane ? g_Xlo : g_Xhi) +
                (((size_t)(b * 192 + j)) << 16) + n0 + q * 8;
            const uint32_t dst = smBase +
                (uint32_t)(bi * GBUF + plane * GPLANE + j * GW + q * 4) * 4u;
            CP_ASYNC16(dst, srcp);
        }
    };

    __syncthreads();           // static rows visible before first MMA
    stage(0, 0);
    CP_COMMIT();

    for (int ci = 0; ci < nChunks; ci++) {
        const int cur = ci & 1;
        if (ci + 1 < nChunks) { stage(ci + 1, 1 - cur); CP_COMMIT(); CP_WAIT(1); }
        else                  { CP_WAIT(0); }
        __syncthreads();

        const uint32_t* hiP = gsm + cur * GBUF;
        const uint32_t* loP = hiP + GPLANE;

#pragma unroll 1
        for (int ks = 0; ks < GCH / 16; ks++) {
            int prev = -1;
            uint32_t ah0 = 0, ah1 = 0, ah2 = 0, ah3 = 0;
            uint32_t al0 = 0, al1 = 0, al2 = 0, al3 = 0;
#pragma unroll
            for (int t = 0; t < 6; t++) {
                if (t < cnt) {
                    const int mt = mtA[t];
                    const int nt = ntA[t];
                    if (mt != prev) {
                        prev = mt;
                        const int arow = mt * 16 + (l >> 2);
                        const uint32_t* ph = hiP + arow * GW + ks * 8;
                        const uint32_t* ph8 = ph + 8 * GW;
                        ah0 = ph[l & 3];  ah2 = ph[(l & 3) + 4];
                        ah1 = ph8[l & 3]; ah3 = ph8[(l & 3) + 4];
                        const uint32_t* ql = loP + arow * GW + ks * 8;
                        const uint32_t* ql8 = ql + 8 * GW;
                        al0 = ql[l & 3];  al2 = ql[(l & 3) + 4];
                        al1 = ql8[l & 3]; al3 = ql8[(l & 3) + 4];
                    }
                    const int brow = nt * 8 + (l >> 2);
                    const uint32_t* pb = hiP + brow * GW + ks * 8;
                    const uint32_t bh0 = pb[l & 3], bh1 = pb[(l & 3) + 4];
                    const uint32_t* pbl = loP + brow * GW + ks * 8;
                    const uint32_t bl0 = pbl[l & 3], bl1 = pbl[(l & 3) + 4];
                    MMA16816(acc[t], ah0, ah1, ah2, ah3, bh0, bh1);
                    MMA16816(acc[t], ah0, ah1, ah2, ah3, bl0, bl1);
                    MMA16816(acc[t], al0, al1, al2, al3, bh0, bh1);
                }
            }
        }
        __syncthreads();   // all warps done reading buf[cur] before re-stage
    }

    float* gp = g_Gp + (size_t)(b * SPLITS + split) * JT * JT;
#pragma unroll
    for (int t = 0; t < 6; t++) {
        if (t < cnt) {
            const int i0 = mtA[t] * 16 + (l >> 2);
            const int j0 = ntA[t] * 8 + 2 * (l & 3);
            *(float2*)&gp[(size_t)i0 * JT + j0] = make_float2(acc[t][0], acc[t][1]);
            *(float2*)&gp[(size_t)(i0 + 8) * JT + j0] = make_float2(acc[t][2], acc[t][3]);
        }
    }
}

// ---------------------------------------------------------------------------
// kernel 2: reduce split-K + mirror
// ---------------------------------------------------------------------------
__global__ void cam_reduceG() {
    const int idx = blockIdx.x * 256 + threadIdx.x;
    const int b = idx / (JT * JT);
    const int rc = idx % (JT * JT);
    const int i = rc / JT, j = rc % JT;
    if (i > j) return;
    const float* gp = g_Gp + (size_t)b * SPLITS * JT * JT + rc;
    float acc = 0.0f;
#pragma unroll 4
    for (int s = 0; s < SPLITS; s++) acc += gp[(size_t)s * JT * JT];
    float* G = g_G + (size_t)b * JT * JT;
    G[i * JT + j] = acc;
    G[j * JT + i] = acc;
}

// ---------------------------------------------------------------------------
// kernel 3: T2[b][i][d] = sum_j G[b][i][j] Wk_aug[d][j]
// ---------------------------------------------------------------------------
__global__ void cam_projT2(const float* __restrict__ Wk,
                           const float* __restrict__ bk) {
    __shared__ float Gs[4][200];
    const int b = blockIdx.y;
    const int i0 = blockIdx.x * 4;
    const int tid = threadIdx.x;

    for (int idx = tid; idx < 4 * 193; idx += 256) {
        const int ii = idx / 193, j = idx % 193;
        if (i0 + ii < 193)
            Gs[ii][j] = g_G[(size_t)b * JT * JT + (size_t)(i0 + ii) * JT + j];
    }
    __syncthreads();

    const int d = tid & 63;
    const int ii = tid >> 6;
    const int i = i0 + ii;
    if (i < 193) {
        float acc = 0.0f;
#pragma unroll 4
        for (int j = 0; j < 192; j++) acc += Wk[d * 192 + j] * Gs[ii][j];
        acc += bk[d] * Gs[ii][192];
        g_T2[(size_t)b * 193 * 64 + i * 64 + d] = acc;
    }
}

// ---------------------------------------------------------------------------
// kernel 4: energy + softmax + M row, fused  (grid (64,4), 256 threads)
// ---------------------------------------------------------------------------
__global__ void cam_energyM(const float* __restrict__ Wq,
                            const float* __restrict__ bq,
                            const float* __restrict__ Wv,
                            const float* __restrict__ bv) {
    __shared__ float part[4][64];
    __shared__ float se[64];
    __shared__ float As[64];
    const int c = blockIdx.x;
    const int b = blockIdx.y;
    const int d = threadIdx.x & 63;
    const int ic = threadIdx.x >> 6;

    const float* T2b = g_T2 + (size_t)b * 193 * 64;
    const int ibeg = ic * 48;
    float e = 0.0f;
#pragma unroll 4
    for (int k = 0; k < 48; k++)
        e += Wq[c * 192 + ibeg + k] * T2b[(ibeg + k) * 64 + d];
    if (ic == 3) e += bq[c] * T2b[192 * 64 + d];
    part[ic][d] = e;
    __syncthreads();

    if (threadIdx.x < 64)
        se[d] = (part[0][d] + part[1][d] + part[2][d] + part[3][d]) * 0.125f;
    __syncthreads();

    if (threadIdx.x < 64) {
        const float e0 = se[d];
        float mx = -1e30f;
#pragma unroll 4
        for (int k = 0; k < 64; k++) mx = fmaxf(mx, se[k]);
        float s = 0.0f;
#pragma unroll 4
        for (int k = 0; k < 64; k++) s += expf(se[k] - mx);
        As[d] = expf(e0 - mx) / s;
    }
    __syncthreads();

    const int j = threadIdx.x;
    if (j < JT) {
        float m = 0.0f;
        if (j < 192) {
#pragma unroll 4
            for (int dd = 0; dd < 64; dd++) m += As[dd] * Wv[dd * 192 + j];
        } else if (j == 192) {
#pragma unroll 4
            for (int dd = 0; dd < 64; dd++) m += As[dd] * bv[dd];
        }
        unsigned short h, lo;
        split_bf16(m, h, lo);
        g_Mhi[(size_t)(b * 64 + c) * JT + j] = h;
        g_Mlo[(size_t)(b * 64 + c) * JT + j] = lo;
    }
}

// ---------------------------------------------------------------------------
// kernel 5: out[b] = M X_aug (R12 path; X staging via cp.async)
// ---------------------------------------------------------------------------
#define OUT_SMEM (2 * 64 * ASTR * 2 + 2 * 64 * OXS * 2)

__global__ __launch_bounds__(256, 2)
void cam_out_mma(float* __restrict__ out) {
    extern __shared__ __align__(16) __nv_bfloat16 osm[];
    __nv_bfloat16* Ahi = osm;                        // [64][216]
    __nv_bfloat16* Alo = Ahi + 64 * ASTR;
    __nv_bfloat16* Xhi = Alo + 64 * ASTR;            // [64][136]
    __nv_bfloat16* Xlo = Xhi + 64 * OXS;

    const int tid = threadIdx.x;
    const int l = tid & 31;
    const int w = tid >> 5;
    const int wm = w >> 2;
    const int wn = w & 3;
    const int b = blockIdx.y;
    const int px0 = blockIdx.x * OTN;

    const uint32_t* mhi = (const uint32_t*)(g_Mhi + (size_t)b * 64 * JT);
    const uint32_t* mlo = (const uint32_t*)(g_Mlo + (size_t)b * 64 * JT);
    for (int idx = tid; idx < 64 * 104; idx += 256) {
        const int c = idx / 104, kk = idx % 104;
        ((uint32_t*)(Ahi + c * ASTR))[kk] = mhi[c * 104 + kk];
        ((uint32_t*)(Alo + c * ASTR))[kk] = mlo[c * 104 + kk];
    }

    float acc[2][4][4];
#pragma unroll
    for (int mi = 0; mi < 2; mi++)
#pragma unroll
        for (int nt = 0; nt < 4; nt++)
#pragma unroll
            for (int q = 0; q < 4; q++) acc[mi][nt][q] = 0.0f;

    const uint32_t xhiB = smem_u32(Xhi);
    const uint32_t xloB = smem_u32(Xlo);

    for (int kc = 0; kc < JT; kc += 64) {
        const int klen = (kc + 64 <= JT) ? 64 : (JT - kc);
        __syncthreads();
        if (kc < 192) {
            // cp.async 16B units, no register pass-through
            for (int u2 = tid; u2 < klen * 16 * 2; u2 += 256) {
                const int plane = (u2 >= klen * 16) ? 1 : 0;
                const int uu = plane ? (u2 - klen * 16) : u2;
                const int kr = uu >> 4;
                const int q = uu & 15;
                const unsigned short* srcp = (plane ? g_Xlo : g_Xhi) +
                    (((size_t)(b * 192 + kc + kr)) << 16) + px0 + q * 8;
                const uint32_t dst = (plane ? xloB : xhiB) +
                    (uint32_t)(kr * OXS + q * 8) * 2u;
                CP_ASYNC16(dst, srcp);
            }
            CP_COMMIT();
            CP_WAIT(0);
        } else {
            for (int u2 = tid; u2 < 16 * 16 * 2; u2 += 256) {
                const int plane = (u2 >= 256) ? 1 : 0;
                const int uu = plane ? (u2 - 256) : u2;
                const int kr = uu >> 4;
                const int q = uu & 15;
                const uint4 val = (plane == 0 && kr == 0)
                    ? make_uint4(0x3F803F80u, 0x3F803F80u, 0x3F803F80u, 0x3F803F80u)
                    : make_uint4(0u, 0u, 0u, 0u);
                *((uint4*)((plane ? Xlo : Xhi) + kr * OXS) + q) = val;
            }
        }
        __syncthreads();

        const int nks = klen / 16;
#pragma unroll 1
        for (int ks = 0; ks < nks; ks++) {
            uint32_t AH[2][4], AL[2][4];
#pragma unroll
            for (int mi = 0; mi < 2; mi++) {
                const int arow = (wm * 2 + mi) * 16 + (l >> 2);
                const uint32_t* ph = (const uint32_t*)(Ahi + arow * ASTR + kc + ks * 16);
                const uint32_t* ph8 = ph + 8 * (ASTR / 2);
                AH[mi][0] = ph[l & 3];  AH[mi][2] = ph[(l & 3) + 4];
                AH[mi][1] = ph8[l & 3]; AH[mi][3] = ph8[(l & 3) + 4];
                const uint32_t* ql = (const uint32_t*)(Alo + arow * ASTR + kc + ks * 16);
                const uint32_t* ql8 = ql + 8 * (ASTR / 2);
                AL[mi][0] = ql[l & 3];  AL[mi][2] = ql[(l & 3) + 4];
                AL[mi][1] = ql8[l & 3]; AL[mi][3] = ql8[(l & 3) + 4];
            }
            const uint32_t rowoff = (uint32_t)(ks * 16 + (l & 15)) * (OXS * 2);
#pragma unroll
            for (int nt = 0; nt < 4; nt++) {
                const uint32_t coloff = (uint32_t)(wn * 32 + nt * 8) * 2;
                uint32_t bh0, bh1, bl0, bl1;
                LDSM_X2_T(bh0, bh1, xhiB + rowoff + coloff);
                LDSM_X2_T(bl0, bl1, xloB + rowoff + coloff);
#pragma unroll
                for (int mi = 0; mi < 2; mi++) {
                    MMA16816(acc[mi][nt], AH[mi][0], AH[mi][1], AH[mi][2], AH[mi][3], bh0, bh1);
                    MMA16816(acc[mi][nt], AH[mi][0], AH[mi][1], AH[mi][2], AH[mi][3], bl0, bl1);
                    MMA16816(acc[mi][nt], AL[mi][0], AL[mi][1], AL[mi][2], AL[mi][3], bh0, bh1);
                }
            }
        }
    }

#pragma unroll
    for (int mi = 0; mi < 2; mi++) {
        const int c0 = (wm * 2 + mi) * 16 + (l >> 2);
#pragma unroll
        for (int nt = 0; nt < 4; nt++) {
            const int px = px0 + wn * 32 + nt * 8 + 2 * (l & 3);
            float* op = out + (size_t)(b * 64 + c0) * NPIX + px;
            *(float2*)op = make_float2(acc[mi][nt][0], acc[mi][nt][1]);
            *(float2*)(op + 8 * NPIX) = make_float2(acc[mi][nt][2], acc[mi][nt][3]);
        }
    }
}

// ---------------------------------------------------------------------------
// launch — presplit + 2 nops keep cam_gram_mma in profiled slot #4
// ---------------------------------------------------------------------------
extern "C" void kernel_launch(void* const* d_in, const int* in_sizes, int n_in,
                              void* d_out, int out_size) {
    const float* rgb = (const float*)d_in[0];
    const float* hsv = (const float*)d_in[1];
    const float* lab = (const float*)d_in[2];
    const float* Wq  = (const float*)d_in[3];
    const float* bq  = (const float*)d_in[4];
    const float* Wk  = (const float*)d_in[5];
    const float* bk  = (const float*)d_in[6];
    const float* Wv  = (const float*)d_in[7];
    const float* bv  = (const float*)d_in[8];
    float* out = (float*)d_out;

    cudaFuncSetAttribute(cam_gram_mma, cudaFuncAttributeMaxDynamicSharedMemorySize, GRAM_SMEM);
    cudaFuncSetAttribute(cam_out_mma, cudaFuncAttributeMaxDynamicSharedMemorySize, OUT_SMEM);

    cam_presplit<<<dim3(6144, 4), 256>>>(rgb, hsv, lab);
    cam_nop<<<1, 32>>>();
    cam_nop<<<1, 32>>>();
    cam_gram_mma<<<dim3(SPLITS, 4, 2), 512, GRAM_SMEM>>>();
    cam_reduceG<<<(4 * JT * JT) / 256, 256>>>();
    cam_projT2<<<dim3(49, 4), 256>>>(Wk, bk);
    cam_energyM<<<dim3(64, 4), 256>>>(Wq, bq, Wv, bv);
    cam_out_mma<<<dim3(NPIX / OTN, 4), 256, OUT_SMEM>>>(out);
}